// round 4
// baseline (speedup 1.0000x reference)
#include <cuda_runtime.h>
#include <cuda_bf16.h>
#include <cstdint>

// Problem constants
#define DFEAT   128
#define KTOP    8
#define DEG     32
#define OUT_CH  128
#define XOUT    120
#define MAXN    10000

// GEMM constants: K = 3 parts * 81 = 243 valid, padded to 256 (16 k-steps of 16)
#define KVALID  243
#define KSTEPS  16
#define RSTRIDE 132       // u32 per row of A/B smem (= 264 bf16; %32 = 4 -> conflict-free frags)
#define SELW    144       // u16 stride of hi/lo selected-feature rows
#define XCHW    9         // padded stride for top-8 exchange rows

__device__ int g_nbr[MAXN * DEG];
__device__ int g_cnt[MAXN];

// ---------------------------------------------------------------------------
// Kernel 1: neighbor extraction (HBM-bound scan of 400MB adjacency)
// ---------------------------------------------------------------------------
__global__ void __launch_bounds__(256) nbr_kernel(const int* __restrict__ adj, int n)
{
    int row = blockIdx.x;
    __shared__ int s_cnt;
    __shared__ int s_idx[DEG];
    if (threadIdx.x == 0) s_cnt = 0;
    __syncthreads();

    const int4* rp = reinterpret_cast<const int4*>(adj + (size_t)row * (size_t)n);
    int nvec = n >> 2;
    for (int i = threadIdx.x; i < nvec; i += blockDim.x) {
        int4 v = rp[i];
        if (v.x | v.y | v.z | v.w) {
            int base = 4 * i;
            if (v.x) { int p = atomicAdd(&s_cnt, 1); if (p < DEG) s_idx[p] = base;     }
            if (v.y) { int p = atomicAdd(&s_cnt, 1); if (p < DEG) s_idx[p] = base + 1; }
            if (v.z) { int p = atomicAdd(&s_cnt, 1); if (p < DEG) s_idx[p] = base + 2; }
            if (v.w) { int p = atomicAdd(&s_cnt, 1); if (p < DEG) s_idx[p] = base + 3; }
        }
    }
    for (int j = (nvec << 2) + threadIdx.x; j < n; j += blockDim.x) {
        if (adj[(size_t)row * (size_t)n + j]) {
            int p = atomicAdd(&s_cnt, 1); if (p < DEG) s_idx[p] = j;
        }
    }
    __syncthreads();
    int c = min(s_cnt, DEG);
    if (threadIdx.x < DEG)
        g_nbr[row * DEG + threadIdx.x] = (threadIdx.x < c) ? s_idx[threadIdx.x] : 0;
    if (threadIdx.x == 0) g_cnt[row] = c;
}

// ---------------------------------------------------------------------------
// bf16 mma.sync wrapper (m16n8k16, row.col, f32 accum)
// ---------------------------------------------------------------------------
__device__ __forceinline__ void mma_bf16(
    float& c0, float& c1, float& c2, float& c3,
    uint32_t a0, uint32_t a1, uint32_t a2, uint32_t a3,
    uint32_t b0, uint32_t b1)
{
    asm volatile(
        "mma.sync.aligned.m16n8k16.row.col.f32.bf16.bf16.f32 "
        "{%0,%1,%2,%3}, {%4,%5,%6,%7}, {%8,%9}, {%0,%1,%2,%3};"
        : "+f"(c0), "+f"(c1), "+f"(c2), "+f"(c3)
        : "r"(a0), "r"(a1), "r"(a2), "r"(a3), "r"(b0), "r"(b1));
}

// ---------------------------------------------------------------------------
// Kernel 2: persistent per-node [top-8 + bf16-split im2col + HMMA GEMM].
// 256 threads. Warp w: m-group mg=w>>1 (rows mg*32..mg*32+31, two m16 tiles),
// n-half nh=w&1 (n-tiles nh?8..14:0..7). A[128xK] weights in smem (built
// once); B[120xK] im2col rebuilt per node. Accumulators in registers.
// ---------------------------------------------------------------------------
__global__ void __launch_bounds__(256) conv_mma_kernel(
    const float* __restrict__ feat,
    const float* __restrict__ w,
    const float* __restrict__ bias,
    float* __restrict__ out, int n)
{
    extern __shared__ uint32_t dynsm[];
    uint32_t* A32 = dynsm;                         // 128 * RSTRIDE u32
    uint32_t* B32 = dynsm + 128 * RSTRIDE;         // 128 * RSTRIDE u32

    __shared__ unsigned short hi_s[9 * SELW];
    __shared__ unsigned short lo_s[9 * SELW];
    __shared__ float s_xchg[128 * XCHW];
    __shared__ int s_nbr[DEG];
    __shared__ int s_cnt;

    const int tid  = threadIdx.x;
    const int wid  = tid >> 5;
    const int lane = tid & 31;
    const int g    = lane >> 2;    // fragment row group
    const int tc   = lane & 3;     // fragment k/col group
    const int mg   = wid >> 1;     // m-group: rows [mg*32, mg*32+32)
    const int nh   = wid & 1;      // n-half
    const int nb   = nh * 8;       // first n-tile
    const int nc   = nh ? 7 : 8;   // n-tile count (15 total)
    const int d    = tid & 127;
    const int half = tid >> 7;

    // per-thread bias for the 4 output rows this thread produces
    float bo[4];
#pragma unroll
    for (int i = 0; i < 4; i++) bo[i] = bias[mg * 32 + i * 8 + g];

    // ---- Build A (split weights) in smem, once ----
    {
        const int o = tid >> 1, h2 = tid & 1;
        uint32_t* arow = A32 + o * RSTRIDE + h2 * 64;
        const float* wrow = w + o * 81;
#pragma unroll
        for (int j = 0; j < 64; j++) {
            unsigned hv[2];
#pragma unroll
            for (int e = 0; e < 2; e++) {
                const int k = h2 * 128 + 2 * j + e;
                unsigned bits = 0;
                if (k < KVALID) {
                    const int p = k / 81, kp = k - p * 81;
                    float wf = wrow[kp];
                    __nv_bfloat16 hb = __float2bfloat16(wf);
                    if (p < 2) bits = (unsigned)__bfloat16_as_ushort(hb);
                    else bits = (unsigned)__bfloat16_as_ushort(
                                    __float2bfloat16(wf - __bfloat162float(hb)));
                }
                hv[e] = bits;
            }
            arow[j] = hv[0] | (hv[1] << 16);
        }
    }
    __syncthreads();

    const uint32_t* Abase = A32 + (size_t)(mg * 32 + g) * RSTRIDE + tc;
    const uint32_t* Bbase = B32 + (size_t)(nb * 8 + g) * RSTRIDE + tc;

    for (int node = blockIdx.x; node < n; node += gridDim.x) {
        if (tid < DEG) s_nbr[tid] = g_nbr[node * DEG + tid];
        if (tid == 0)  s_cnt = g_cnt[node];
        __syncthreads();
        const int cnt = s_cnt;

        // ---- Stage 1a: each half-thread gathers 16 neighbors, keeps top-8 ----
        float t8[KTOP];
#pragma unroll
        for (int k = 0; k < KTOP; k++) t8[k] = -INFINITY;
        {
            const int jb = half * 16;
            const int je = min(cnt, jb + 16);
            for (int j = jb; j < je; j++) {
                float v = __ldg(&feat[(size_t)s_nbr[j] * DFEAT + d]);
                if (v > t8[KTOP - 1]) {
                    t8[KTOP - 1] = v;
#pragma unroll
                    for (int k = KTOP - 2; k >= 0; k--) {
                        if (t8[k + 1] > t8[k]) {
                            float tmp = t8[k]; t8[k] = t8[k + 1]; t8[k + 1] = tmp;
                        }
                    }
                }
            }
        }
        if (half) {
#pragma unroll
            for (int k = 0; k < KTOP; k++) s_xchg[d * XCHW + k] = t8[k];
        }
        __syncthreads();

        // ---- Stage 1b: merge halves, apply zero-pad semantics, write hi/lo ----
        if (tid < 128) {
            float ov[KTOP];
#pragma unroll
            for (int k = 0; k < KTOP; k++) ov[k] = s_xchg[d * XCHW + k];
            float m8[KTOP];
            int ia = 0, ib = 0;
#pragma unroll
            for (int i = 0; i < KTOP; i++) {
                bool ta = (ib >= KTOP) || (ia < KTOP && t8[ia] >= ov[ib]);
                m8[i] = ta ? t8[ia] : ov[ib];
                if (ta) ia++; else ib++;
            }
#pragma unroll
            for (int k = 0; k < KTOP; k++)
                if (m8[k] == -INFINITY) m8[k] = 0.0f;
            if (cnt < KTOP) {
#pragma unroll
                for (int a = 1; a < KTOP; a++) {
#pragma unroll
                    for (int bq = a; bq >= 1; bq--) {
                        if (m8[bq] > m8[bq - 1]) {
                            float tmp = m8[bq - 1]; m8[bq - 1] = m8[bq]; m8[bq] = tmp;
                        }
                    }
                }
            }
            float rows[9];
            rows[0] = feat[(size_t)node * DFEAT + d];
#pragma unroll
            for (int k = 0; k < KTOP; k++) rows[1 + k] = m8[k];
#pragma unroll
            for (int c = 0; c < 9; c++) {
                float v = rows[c];
                __nv_bfloat16 hb = __float2bfloat16(v);
                float r = v - __bfloat162float(hb);
                hi_s[c * SELW + d] = __bfloat16_as_ushort(hb);
                lo_s[c * SELW + d] = __bfloat16_as_ushort(__float2bfloat16(r));
            }
        }
        __syncthreads();

        // ---- Stage 2: B im2col build (rows x<120 only; 2 threads per row) ----
        if (d < XOUT) {
            uint32_t* brow = B32 + d * RSTRIDE + half * 64;
#pragma unroll
            for (int j = 0; j < 64; j++) {
                unsigned hv[2];
#pragma unroll
                for (int e = 0; e < 2; e++) {
                    const int k = half * 128 + 2 * j + e;
                    unsigned bits = 0;
                    if (k < KVALID) {
                        const int p = k / 81, kp = k - 81 * p;
                        const int c = kp / 9, t = kp - 9 * c;
                        const unsigned short* src = (p == 1) ? lo_s : hi_s;
                        bits = (unsigned)src[c * SELW + d + t];
                    }
                    hv[e] = bits;
                }
                brow[j] = hv[0] | (hv[1] << 16);
            }
        }
        __syncthreads();

        // ---- Stage 3: GEMM via mma.sync (accumulate in registers) ----
        float acc[2][8][4];
#pragma unroll
        for (int i = 0; i < 2; i++)
#pragma unroll
            for (int t = 0; t < 8; t++)
#pragma unroll
                for (int q = 0; q < 4; q++) acc[i][t][q] = 0.0f;

#pragma unroll 2
        for (int ks = 0; ks < KSTEPS; ks++) {
            uint32_t a[2][4];
#pragma unroll
            for (int i = 0; i < 2; i++) {
                const uint32_t* ap = Abase + i * 16 * RSTRIDE + ks * 8;
                a[i][0] = ap[0];
                a[i][1] = ap[8 * RSTRIDE];
                a[i][2] = ap[4];
                a[i][3] = ap[8 * RSTRIDE + 4];
            }
#pragma unroll
            for (int t = 0; t < 8; t++) {
                if (t < nc) {
                    const uint32_t* bp = Bbase + t * 8 * RSTRIDE + ks * 8;
                    uint32_t b0 = bp[0];
                    uint32_t b1 = bp[4];
                    mma_bf16(acc[0][t][0], acc[0][t][1], acc[0][t][2], acc[0][t][3],
                             a[0][0], a[0][1], a[0][2], a[0][3], b0, b1);
                    mma_bf16(acc[1][t][0], acc[1][t][1], acc[1][t][2], acc[1][t][3],
                             a[1][0], a[1][1], a[1][2], a[1][3], b0, b1);
                }
            }
        }

        // ---- Stage 4: epilogue (bias + float2 stores) ----
        {
            float* obase = out + (size_t)node * (OUT_CH * XOUT);
#pragma unroll
            for (int i = 0; i < 2; i++) {
                const int ra = mg * 32 + i * 16 + g;
                const float ba = bo[i * 2];
                const float bb = bo[i * 2 + 1];
#pragma unroll
                for (int t = 0; t < 8; t++) {
                    if (t < nc) {
                        const int x0 = (nb + t) * 8 + tc * 2;
                        float2 v0 = make_float2(acc[i][t][0] + ba, acc[i][t][1] + ba);
                        float2 v1 = make_float2(acc[i][t][2] + bb, acc[i][t][3] + bb);
                        *reinterpret_cast<float2*>(obase + (size_t)ra * XOUT + x0) = v0;
                        *reinterpret_cast<float2*>(obase + (size_t)(ra + 8) * XOUT + x0) = v1;
                    }
                }
            }
        }
        __syncthreads();   // protect B/hi/lo/s_nbr before next node
    }
}

// ---------------------------------------------------------------------------
extern "C" void kernel_launch(void* const* d_in, const int* in_sizes, int n_in,
                              void* d_out, int out_size)
{
    const float* feat = (const float*)d_in[0];
    const int*   adj  = (const int*)d_in[1];
    const float* w    = (const float*)d_in[2];
    const float* b    = (const float*)d_in[3];
    float*       out  = (float*)d_out;

    int n = in_sizes[0] / DFEAT;
    if (n > MAXN) n = MAXN;

    const int dyn_bytes = 2 * 128 * RSTRIDE * sizeof(uint32_t);  // ~135 KB
    cudaFuncSetAttribute(conv_mma_kernel, cudaFuncAttributeMaxDynamicSharedMemorySize,
                         dyn_bytes);

    nbr_kernel<<<n, 256>>>(adj, n);
    conv_mma_kernel<<<152, 256, dyn_bytes>>>(feat, w, b, out, n);
}

// round 5
// speedup vs baseline: 1.4790x; 1.4790x over previous
#include <cuda_runtime.h>
#include <cuda_bf16.h>
#include <cstdint>

// Problem constants
#define DFEAT   128
#define KTOP    8
#define DEG     32
#define OUT_CH  128
#define XOUT    120
#define MAXN    10000

// GEMM constants: K = 3 parts * 81 = 243 valid, padded to 256 = 16 k-steps
#define KVALID  243
#define KSTEPS  16
#define RST     136        // u32 row stride for A/B smem (mod 32 = 8 -> conflict-free LDS.64)
#define SELW2   136        // u32 row stride for staged sel rows
#define NT      15         // n-tiles (120 / 8)

__device__ int g_cnt[MAXN];
__device__ unsigned g_sel[MAXN * 9 * DFEAT];   // packed bf16: hi | lo<<16, [node][c][d]

// ---------------------------------------------------------------------------
// bf16 mma.sync wrapper (m16n8k16, row.col, f32 accum)
// ---------------------------------------------------------------------------
__device__ __forceinline__ void mma_bf16(
    float& c0, float& c1, float& c2, float& c3,
    uint32_t a0, uint32_t a1, uint32_t a2, uint32_t a3,
    uint32_t b0, uint32_t b1)
{
    asm volatile(
        "mma.sync.aligned.m16n8k16.row.col.f32.bf16.bf16.f32 "
        "{%0,%1,%2,%3}, {%4,%5,%6,%7}, {%8,%9}, {%0,%1,%2,%3};"
        : "+f"(c0), "+f"(c1), "+f"(c2), "+f"(c3)
        : "r"(a0), "r"(a1), "r"(a2), "r"(a3), "r"(b0), "r"(b1));
}

// ---------------------------------------------------------------------------
// Kernel 1: fused adjacency scan + neighbor gather + per-feature top-8 +
// bf16 hi/lo split. One block (256 threads) per node. The scan is HBM-bound
// (400MB); the gather/top-8 tail hides under other blocks' scans.
// ---------------------------------------------------------------------------
__global__ void __launch_bounds__(256) scan_gather_kernel(
    const int* __restrict__ adj, const float* __restrict__ feat, int n)
{
    const int node = blockIdx.x;
    __shared__ int s_cnt;
    __shared__ int s_idx[DEG];
    if (threadIdx.x == 0) s_cnt = 0;
    __syncthreads();

    // ---- scan adjacency row ----
    const int4* rp = reinterpret_cast<const int4*>(adj + (size_t)node * (size_t)n);
    int nvec = n >> 2;
    for (int i = threadIdx.x; i < nvec; i += blockDim.x) {
        int4 v = rp[i];
        if (v.x | v.y | v.z | v.w) {
            int base = 4 * i;
            if (v.x) { int p = atomicAdd(&s_cnt, 1); if (p < DEG) s_idx[p] = base;     }
            if (v.y) { int p = atomicAdd(&s_cnt, 1); if (p < DEG) s_idx[p] = base + 1; }
            if (v.z) { int p = atomicAdd(&s_cnt, 1); if (p < DEG) s_idx[p] = base + 2; }
            if (v.w) { int p = atomicAdd(&s_cnt, 1); if (p < DEG) s_idx[p] = base + 3; }
        }
    }
    for (int j = (nvec << 2) + threadIdx.x; j < n; j += blockDim.x) {
        if (adj[(size_t)node * (size_t)n + j]) {
            int p = atomicAdd(&s_cnt, 1); if (p < DEG) s_idx[p] = j;
        }
    }
    __syncthreads();
    const int cnt = min(s_cnt, DEG);

    // ---- gather + per-feature top-8 (threads < 128; d = tid) ----
    if (threadIdx.x < DFEAT) {
        const int d = threadIdx.x;
        float t8[KTOP];
#pragma unroll
        for (int k = 0; k < KTOP; k++) t8[k] = -INFINITY;
        for (int j = 0; j < cnt; j++) {
            float v = __ldg(&feat[(size_t)s_idx[j] * DFEAT + d]);
            if (v > t8[KTOP - 1]) {
                t8[KTOP - 1] = v;
#pragma unroll
                for (int k = KTOP - 2; k >= 0; k--) {
                    if (t8[k + 1] > t8[k]) {
                        float tmp = t8[k]; t8[k] = t8[k + 1]; t8[k + 1] = tmp;
                    }
                }
            }
        }
        // reference semantics: missing (-inf) -> 0, then resort descending
#pragma unroll
        for (int k = 0; k < KTOP; k++)
            if (t8[k] == -INFINITY) t8[k] = 0.0f;
        if (cnt < KTOP) {
#pragma unroll
            for (int a = 1; a < KTOP; a++) {
#pragma unroll
                for (int bq = a; bq >= 1; bq--) {
                    if (t8[bq] > t8[bq - 1]) {
                        float tmp = t8[bq - 1]; t8[bq - 1] = t8[bq]; t8[bq] = tmp;
                    }
                }
            }
        }
        float rows[9];
        rows[0] = feat[(size_t)node * DFEAT + d];
#pragma unroll
        for (int k = 0; k < KTOP; k++) rows[1 + k] = t8[k];
        unsigned* sp = g_sel + (size_t)node * (9 * DFEAT) + d;
#pragma unroll
        for (int c = 0; c < 9; c++) {
            float v = rows[c];
            __nv_bfloat16 hb = __float2bfloat16(v);
            float r = v - __bfloat162float(hb);
            unsigned hi = (unsigned)__bfloat16_as_ushort(hb);
            unsigned lo = (unsigned)__bfloat16_as_ushort(__float2bfloat16(r));
            sp[c * DFEAT] = hi | (lo << 16);
        }
    }
}

// ---------------------------------------------------------------------------
// Kernel 2: persistent im2col + HMMA GEMM. 256 threads, 148 CTAs.
// A[128x256] (3-part bf16 split weights) lives in REGISTERS (warp w owns
// m16 tile rows [w*16, w*16+16)); B[120x256] im2col rebuilt per node in smem.
// k-interleaved layout: u32 pos = ks*8 + tc*2 + khalf  (khalf = k%16 >= 8),
// so each mma fragment is one LDS.64.
// ---------------------------------------------------------------------------
__global__ void __launch_bounds__(256) gemm_kernel(
    const float* __restrict__ w,
    const float* __restrict__ bias,
    float* __restrict__ out, int n)
{
    extern __shared__ uint32_t Bsm[];            // 128 * RST u32 (A staging, then B)
    __shared__ uint32_t sel_sm[9 * SELW2];

    const int tid  = threadIdx.x;
    const int wid  = tid >> 5;
    const int lane = tid & 31;
    const int g    = lane >> 2;
    const int tc   = lane & 3;

    // zero sel tail columns once (rebuilt region is d<128 only)
    if (tid < 9 * 8) {
        int c = tid >> 3;
        sel_sm[c * SELW2 + 128 + (tid & 7)] = 0u;
    }

    // ---- stage A (split weights) into smem with k-interleaved layout ----
    {
        const int o = tid >> 1, h2 = tid & 1;
        uint32_t* arow = Bsm + o * RST + h2 * 64;
        const float* wrow = w + o * 81;
#pragma unroll
        for (int j4 = 0; j4 < 16; j4++) {
            uint32_t vv[4];
#pragma unroll
            for (int u = 0; u < 4; u++) {
                const int pos = h2 * 64 + j4 * 4 + u;
                const int ks = pos >> 3, q = pos & 7, tcq = q >> 1, kh = q & 1;
                const int kb = ks * 16 + kh * 8 + tcq * 2;
                unsigned hv[2];
#pragma unroll
                for (int e = 0; e < 2; e++) {
                    const int k = kb + e;
                    unsigned bits = 0;
                    if (k < KVALID) {
                        const int p = k / 81, kp = k - 81 * p;
                        float wf = wrow[kp];
                        __nv_bfloat16 hb = __float2bfloat16(wf);
                        if (p < 2) bits = (unsigned)__bfloat16_as_ushort(hb);
                        else bits = (unsigned)__bfloat16_as_ushort(
                                        __float2bfloat16(wf - __bfloat162float(hb)));
                    }
                    hv[e] = bits;
                }
                vv[u] = hv[0] | (hv[1] << 16);
            }
            *reinterpret_cast<uint4*>(arow + j4 * 4) =
                make_uint4(vv[0], vv[1], vv[2], vv[3]);
        }
    }
    __syncthreads();

    // ---- load this warp's A fragments into registers (one m16 tile) ----
    uint32_t a[KSTEPS][4];
    {
        const uint32_t* r0 = Bsm + (size_t)(wid * 16 + g) * RST + tc * 2;
        const uint32_t* r1 = r0 + 8 * RST;
#pragma unroll
        for (int ks = 0; ks < KSTEPS; ks++) {
            uint2 x = *reinterpret_cast<const uint2*>(r0 + ks * 8);
            uint2 y = *reinterpret_cast<const uint2*>(r1 + ks * 8);
            a[ks][0] = x.x; a[ks][2] = x.y;
            a[ks][1] = y.x; a[ks][3] = y.y;
        }
    }
    __syncthreads();   // A consumed from smem; Bsm becomes the B buffer

    const float b0v = bias[wid * 16 + g];
    const float b1v = bias[wid * 16 + g + 8];

    // prefetch sel for first node
    uint32_t selr[5];
    int node = blockIdx.x;
    if (node < n) {
#pragma unroll
        for (int q = 0; q < 5; q++) {
            int i = tid + q * 256;
            if (i < 1152) selr[q] = g_sel[(size_t)node * 1152 + i];
        }
    }

    for (; node < n; node += gridDim.x) {
        // stage sel into smem
#pragma unroll
        for (int q = 0; q < 5; q++) {
            int i = tid + q * 256;
            if (i < 1152) sel_sm[(i >> 7) * SELW2 + (i & 127)] = selr[q];
        }
        __syncthreads();

        // ---- build B (rows d<120; 2 threads per row) ----
        if (tid < 240) {
            const int d = tid >> 1, h2 = tid & 1;
            uint32_t* brow = Bsm + (size_t)d * RST + h2 * 64;
#pragma unroll
            for (int j4 = 0; j4 < 16; j4++) {
                uint32_t vv[4];
#pragma unroll
                for (int u = 0; u < 4; u++) {
                    const int pos = h2 * 64 + j4 * 4 + u;
                    const int ks = pos >> 3, q = pos & 7, tcq = q >> 1, kh = q & 1;
                    const int kb = ks * 16 + kh * 8 + tcq * 2;
                    unsigned hv[2];
#pragma unroll
                    for (int e = 0; e < 2; e++) {
                        const int k = kb + e;
                        unsigned bits = 0;
                        if (k < KVALID) {
                            const int p = k / 81, kp = k - 81 * p;
                            const int c = kp / 9, t = kp - 9 * c;
                            uint32_t pk = sel_sm[c * SELW2 + d + t];
                            bits = (p == 1) ? (pk >> 16) : (pk & 0xffffu);
                        }
                        hv[e] = bits;
                    }
                    vv[u] = hv[0] | (hv[1] << 16);
                }
                *reinterpret_cast<uint4*>(brow + j4 * 4) =
                    make_uint4(vv[0], vv[1], vv[2], vv[3]);
            }
        }
        __syncthreads();

        // prefetch next node's sel (LDG latency hides under the MMA below)
        {
            int nxt = node + gridDim.x;
            if (nxt < n) {
#pragma unroll
                for (int q = 0; q < 5; q++) {
                    int i = tid + q * 256;
                    if (i < 1152) selr[q] = g_sel[(size_t)nxt * 1152 + i];
                }
            }
        }

        // ---- MMA: warp = one m16 tile x all 15 n-tiles, K=256 ----
        float acc[NT][4];
#pragma unroll
        for (int t = 0; t < NT; t++)
#pragma unroll
            for (int q = 0; q < 4; q++) acc[t][q] = 0.0f;

        const uint32_t* Bb = Bsm + (size_t)g * RST + tc * 2;
#pragma unroll
        for (int ks = 0; ks < KSTEPS; ks++) {
#pragma unroll
            for (int t = 0; t < NT; t++) {
                uint2 b = *reinterpret_cast<const uint2*>(Bb + (size_t)(t * 8) * RST + ks * 8);
                mma_bf16(acc[t][0], acc[t][1], acc[t][2], acc[t][3],
                         a[ks][0], a[ks][1], a[ks][2], a[ks][3], b.x, b.y);
            }
        }

        // ---- epilogue: bias + float2 stores ----
        {
            float* obase = out + (size_t)node * (OUT_CH * XOUT);
            const int r0 = wid * 16 + g;
            float* p0 = obase + (size_t)r0 * XOUT + tc * 2;
            float* p1 = obase + (size_t)(r0 + 8) * XOUT + tc * 2;
#pragma unroll
            for (int t = 0; t < NT; t++) {
                *reinterpret_cast<float2*>(p0 + t * 8) =
                    make_float2(acc[t][0] + b0v, acc[t][1] + b0v);
                *reinterpret_cast<float2*>(p1 + t * 8) =
                    make_float2(acc[t][2] + b1v, acc[t][3] + b1v);
            }
        }
        __syncthreads();   // B + sel_sm consumed before next iteration
    }
}

// ---------------------------------------------------------------------------
extern "C" void kernel_launch(void* const* d_in, const int* in_sizes, int n_in,
                              void* d_out, int out_size)
{
    const float* feat = (const float*)d_in[0];
    const int*   adj  = (const int*)d_in[1];
    const float* w    = (const float*)d_in[2];
    const float* b    = (const float*)d_in[3];
    float*       out  = (float*)d_out;

    int n = in_sizes[0] / DFEAT;
    if (n > MAXN) n = MAXN;

    const int dyn_bytes = 128 * RST * sizeof(uint32_t);   // 69,632 B
    cudaFuncSetAttribute(gemm_kernel, cudaFuncAttributeMaxDynamicSharedMemorySize,
                         dyn_bytes);

    scan_gather_kernel<<<n, 256>>>(adj, feat, n);
    gemm_kernel<<<148, 256, dyn_bytes>>>(w, b, out, n);
}